// round 1
// baseline (speedup 1.0000x reference)
#include <cuda_runtime.h>
#include <cuda_bf16.h>
#include <math.h>

// SpatialGRU: B=256, C=128, L1=L2=32, U=128
// W: (512, 896) rows = [h_top(128), h_left(128), h_diag(128), s(128)], cols = [wr(384), wz(512)]
// Umat: (384,128) rows = [h_left, h_top, h_diag]; w_ij: (128,128); bias: (1024,)
// Output = h at cell (31,31): (256,128) fp32.

#define Bsz   256
#define Cdim  128
#define Ldim  32
#define Udim  128
#define K1    512      // 3U + C
#define N1    896      // 7U
#define BM    16       // batch rows per block

// scratch (device globals: no allocation allowed)
__device__ float g_T[1024 * 256 * 128];   // T[p][b][c], p = i*32+j   (128 MB)
__device__ float g_H[1024 * 256 * 128];   // H[p][b][u]               (128 MB)
__device__ float g_U2[512 * 128];         // [Umat(384 rows); w_ij(128 rows)]

// ---------------------------------------------------------------------------
// Transpose inputs (B,C,L1,L2) -> T[p][b][c]  (treat as (32768 x 1024) -> (1024 x 32768))
__global__ void transpose_kernel(const float* __restrict__ in) {
    __shared__ float tile[32][33];
    int x  = blockIdx.x * 32 + threadIdx.x;   // p
    int y0 = blockIdx.y * 32;                 // bc = b*128+c
#pragma unroll
    for (int r = 0; r < 4; r++) {
        int y = y0 + threadIdx.y + r * 8;
        tile[threadIdx.y + r * 8][threadIdx.x] = in[(size_t)y * 1024 + x];
    }
    __syncthreads();
    int xo  = blockIdx.y * 32 + threadIdx.x;  // bc
    int yo0 = blockIdx.x * 32;                // p
#pragma unroll
    for (int r = 0; r < 4; r++) {
        int yo = yo0 + threadIdx.y + r * 8;
        g_T[(size_t)yo * 32768 + xo] = tile[threadIdx.x][threadIdx.y + r * 8];
    }
}

// Build extended U matrix: rows 0:384 = Umat, rows 384:512 = w_ij
__global__ void prep_u2_kernel(const float* __restrict__ Umat, const float* __restrict__ w_ij) {
    int idx = blockIdx.x * 256 + threadIdx.x;
    if (idx < 512 * 128) {
        int k = idx >> 7;
        g_U2[idx] = (k < 384) ? Umat[idx] : w_ij[idx - 384 * 128];
    }
}

// ---------------------------------------------------------------------------
// One anti-diagonal: grid = (ncells, 256/BM), 256 threads.
// Block computes h(i,j) for BM batch rows: GEMM1 (BM x 896, K=512), gates,
// GEMM2 (BM x 128, K=512), epilogue. All block-local via shared memory.
__global__ void diag_kernel(int d, const float* __restrict__ W,
                            const float* __restrict__ bias, float* __restrict__ out) {
    extern __shared__ float sm[];
    float* qs  = sm;                       // BM*512  : q = [h_top, h_left, h_diag, s]
    float* rzs = qs + BM * 512;            // BM*896  : gate pre-acts -> r / softmax(z)
    float* wt  = rzs + BM * 896;           // 32*128  : W / U2 K-tile
    float* ut  = wt + 32 * 128;            // BM*32   : GEMM2 A K-tile

    const int i0 = (d > 31) ? d - 31 : 0;
    const int i  = i0 + blockIdx.x;
    const int j  = d - i;
    const int p  = i * 32 + j;
    const int m0 = blockIdx.y * BM;

    const float* Htop  = (i > 0)          ? &g_H[(((size_t)p - 32) * 256 + m0) * 128] : nullptr;
    const float* Hleft = (j > 0)          ? &g_H[(((size_t)p -  1) * 256 + m0) * 128] : nullptr;
    const float* Hdiag = (i > 0 && j > 0) ? &g_H[(((size_t)p - 33) * 256 + m0) * 128] : nullptr;
    const float* Tp    = &g_T[((size_t)p * 256 + m0) * 128];

    const int tid = threadIdx.x;
    const int ty  = tid >> 5;       // 0..7
    const int tx  = tid & 31;
    const int r0  = ty * 2;         // 2 rows per warp-lane-group

    // ---- assemble q tile into smem (vectorized) ----
    {
        float4* qs4 = (float4*)qs;
        const float4 z4 = make_float4(0.f, 0.f, 0.f, 0.f);
        for (int idx = tid; idx < BM * 128; idx += 256) {  // BM*512/4 float4s
            int m  = idx >> 7;
            int k4 = idx & 127;          // float4 index in [0,128), k = 4*k4
            float4 v;
            if (k4 < 32)       v = Htop  ? ((const float4*)Htop )[m * 32 + k4]        : z4;
            else if (k4 < 64)  v = Hleft ? ((const float4*)Hleft)[m * 32 + (k4 - 32)] : z4;
            else if (k4 < 96)  v = Hdiag ? ((const float4*)Hdiag)[m * 32 + (k4 - 64)] : z4;
            else               v = ((const float4*)Tp)[m * 32 + (k4 - 96)];
            qs4[idx] = v;
        }
    }
    __syncthreads();

    // ---- GEMM1: rz[m][n] = sum_k q[m][k] * W[k][n] ----
    for (int nc = 0; nc < N1; nc += 128) {
        float acc[2][4] = {};
        for (int kt = 0; kt < K1; kt += 32) {
            {   // stage W tile (32 x 128) as float4
                float4* wt4 = (float4*)wt;
                const float4* Wg = (const float4*)(W + (size_t)kt * N1 + nc);
                for (int l = tid; l < 32 * 32; l += 256) {
                    int kk = l >> 5, n4 = l & 31;
                    wt4[kk * 32 + n4] = Wg[(size_t)kk * (N1 / 4) + n4];
                }
            }
            __syncthreads();
#pragma unroll
            for (int kk = 0; kk < 32; kk++) {
                float a0 = qs[(r0 + 0) * 512 + kt + kk];
                float a1 = qs[(r0 + 1) * 512 + kt + kk];
                float4 b = *(const float4*)&wt[kk * 128 + tx * 4];
                acc[0][0] += a0 * b.x; acc[0][1] += a0 * b.y;
                acc[0][2] += a0 * b.z; acc[0][3] += a0 * b.w;
                acc[1][0] += a1 * b.x; acc[1][1] += a1 * b.y;
                acc[1][2] += a1 * b.z; acc[1][3] += a1 * b.w;
            }
            __syncthreads();
        }
#pragma unroll
        for (int r = 0; r < 2; r++)
            *(float4*)&rzs[(r0 + r) * 896 + nc + tx * 4] =
                make_float4(acc[r][0], acc[r][1], acc[r][2], acc[r][3]);
    }
    __syncthreads();

    // ---- gates: r = hard_sigmoid(rz[:,:384]+br); z groups softmaxed in place ----
    for (int idx = tid; idx < BM * 384; idx += 256) {
        int m = idx / 384, n = idx - m * 384;
        float v = rzs[m * 896 + n] + bias[n];
        rzs[m * 896 + n] = fminf(fmaxf(0.2f * v + 0.5f, 0.0f), 1.0f);
    }
    for (int idx = tid; idx < BM * 128; idx += 256) {
        int m = idx >> 7, u = idx & 127;
        float* zp = &rzs[m * 896 + 384 + u];
        float z0 = zp[0]   + bias[384 + u];
        float z1 = zp[128] + bias[512 + u];
        float z2 = zp[256] + bias[640 + u];
        float z3 = zp[384] + bias[768 + u];
        float mx = fmaxf(fmaxf(z0, z1), fmaxf(z2, z3));
        float e0 = expf(z0 - mx), e1 = expf(z1 - mx), e2 = expf(z2 - mx), e3 = expf(z3 - mx);
        float inv = 1.0f / (e0 + e1 + e2 + e3);
        zp[0] = e0 * inv; zp[128] = e1 * inv; zp[256] = e2 * inv; zp[384] = e3 * inv;
    }
    __syncthreads();

    // ---- GEMM2: uu[m][u] = sum_k uin[m][k] * U2[k][u]
    //      uin = [r(0:128)*h_left, r(128:256)*h_top, r(256:384)*h_diag, s_ij]
    float acc2[2][4] = {};
    for (int kt = 0; kt < 512; kt += 32) {
        for (int l = tid; l < BM * 32; l += 256) {
            int m = l >> 5, kk = l & 31;
            int k = kt + kk;
            float v;
            if (k < 128)      v = rzs[m * 896 + k] * qs[m * 512 + 128 + k];      // r * h_left
            else if (k < 256) v = rzs[m * 896 + k] * qs[m * 512 + (k - 128)];    // r * h_top
            else if (k < 384) v = rzs[m * 896 + k] * qs[m * 512 + k];            // r * h_diag
            else              v = qs[m * 512 + k];                               // s_ij
            ut[m * 32 + kk] = v;
        }
        {   // stage U2 tile (32 x 128)
            float4* wt4 = (float4*)wt;
            const float4* Ug = (const float4*)(g_U2 + (size_t)kt * 128);
            for (int l = tid; l < 32 * 32; l += 256) wt4[l] = Ug[l];
        }
        __syncthreads();
#pragma unroll
        for (int kk = 0; kk < 32; kk++) {
            float a0 = ut[(r0 + 0) * 32 + kk];
            float a1 = ut[(r0 + 1) * 32 + kk];
            float4 b = *(const float4*)&wt[kk * 128 + tx * 4];
            acc2[0][0] += a0 * b.x; acc2[0][1] += a0 * b.y;
            acc2[0][2] += a0 * b.z; acc2[0][3] += a0 * b.w;
            acc2[1][0] += a1 * b.x; acc2[1][1] += a1 * b.y;
            acc2[1][2] += a1 * b.z; acc2[1][3] += a1 * b.w;
        }
        __syncthreads();
    }

    // ---- epilogue: h = zl*hl + zt*ht + zd*hd + zi*tanh(uu + b_ij) ----
    const size_t hb = (size_t)p * 256 + m0;
#pragma unroll
    for (int r = 0; r < 2; r++) {
        int m = r0 + r;
        float o[4];
#pragma unroll
        for (int s = 0; s < 4; s++) {
            int u = tx * 4 + s;
            float zi = rzs[m * 896 + 384 + u];
            float zl = rzs[m * 896 + 512 + u];
            float zt = rzs[m * 896 + 640 + u];
            float zd = rzs[m * 896 + 768 + u];
            float hl = qs[m * 512 + 128 + u];
            float ht = qs[m * 512 + u];
            float hd = qs[m * 512 + 256 + u];
            float hstar = tanhf(acc2[r][s] + bias[896 + u]);
            o[s] = zl * hl + zt * ht + zd * hd + zi * hstar;
        }
        float4 v = make_float4(o[0], o[1], o[2], o[3]);
        *(float4*)&g_H[(hb + m) * 128 + tx * 4] = v;
        if (p == 1023) *(float4*)&out[(size_t)(m0 + m) * 128 + tx * 4] = v;
    }
}

// ---------------------------------------------------------------------------
#define SMEM_BYTES ((BM * 512 + BM * 896 + 32 * 128 + BM * 32) * 4)

extern "C" void kernel_launch(void* const* d_in, const int* in_sizes, int n_in,
                              void* d_out, int out_size) {
    const float* inputs = (const float*)d_in[0];
    const float* W      = (const float*)d_in[1];
    const float* Umat   = (const float*)d_in[2];
    const float* bias   = (const float*)d_in[3];
    const float* w_ij   = (const float*)d_in[4];
    float* out = (float*)d_out;

    cudaFuncSetAttribute(diag_kernel, cudaFuncAttributeMaxDynamicSharedMemorySize, SMEM_BYTES);

    transpose_kernel<<<dim3(32, 1024), dim3(32, 8)>>>(inputs);
    prep_u2_kernel<<<256, 256>>>(Umat, w_ij);

    for (int d = 0; d <= 62; d++) {
        int i0 = (d > 31) ? d - 31 : 0;
        int i1 = (d < 31) ? d : 31;
        int nc = i1 - i0 + 1;
        diag_kernel<<<dim3(nc, Bsz / BM), 256, SMEM_BYTES>>>(d, W, bias, out);
    }
    (void)in_sizes; (void)n_in; (void)out_size;
}

// round 2
// speedup vs baseline: 4.2468x; 4.2468x over previous
#include <cuda_runtime.h>
#include <cstdint>
#include <math.h>

// SpatialGRU: B=256, C=128, L1=L2=32, U=128
// Per diagonal d (63 of them): K1 = fused GEMM1(q@Wp)+gates, K2 = GEMM2+epilogue.
// tf32 mma.sync m16n8k8, 128x128x32 block tiles, cp.async double buffering.

#define NP  1024
#define BSZ 256

// ---- device scratch (no allocation allowed) ----
__device__ float g_T [NP * BSZ * 128];   // s, tf32-rounded (MMA operand only)
__device__ float g_H [NP * BSZ * 128];   // h, full fp32 (epilogue operand)
__device__ float g_Hr[NP * BSZ * 128];   // h, tf32-rounded (MMA operand)
__device__ float g_Wp[512 * 896];        // col-permuted W, tf32-rounded
__device__ float g_U2[512 * 128];        // [Umat; w_ij], tf32-rounded
__device__ float g_bP[896];              // permuted bias (r|z part)
__device__ float g_A2[8192 * 384];       // GEMM2 A (r*h parts), tf32-rounded
__device__ float g_Z [8192 * 512];       // softmaxed gates, layout [m][u*4+g], g=zi,zl,zt,zd

__device__ __forceinline__ float to_tf32(float x) {
    float r; asm("cvt.rna.tf32.f32 %0, %1;" : "=f"(r) : "f"(x)); return r;
}
__device__ __forceinline__ void mma8(float* c, const uint32_t* a, const uint32_t* b) {
    asm volatile("mma.sync.aligned.m16n8k8.row.col.f32.tf32.tf32.f32 "
        "{%0,%1,%2,%3},{%4,%5,%6,%7},{%8,%9},{%0,%1,%2,%3};"
        : "+f"(c[0]), "+f"(c[1]), "+f"(c[2]), "+f"(c[3])
        : "r"(a[0]), "r"(a[1]), "r"(a[2]), "r"(a[3]), "r"(b[0]), "r"(b[1]));
}
__device__ __forceinline__ void cp16(uint32_t dst, const void* src, int sz) {
    asm volatile("cp.async.cg.shared.global [%0], [%1], 16, %2;" :: "r"(dst), "l"(src), "r"(sz));
}

// ---------------------------------------------------------------------------
// setup kernels
__global__ void transpose_kernel(const float* __restrict__ in) {
    __shared__ float tile[32][33];
    int x  = blockIdx.x * 32 + threadIdx.x;   // p
    int y0 = blockIdx.y * 32;                 // bc
#pragma unroll
    for (int r = 0; r < 4; r++) {
        int y = y0 + threadIdx.y + r * 8;
        tile[threadIdx.y + r * 8][threadIdx.x] = in[(size_t)y * 1024 + x];
    }
    __syncthreads();
    int xo  = blockIdx.y * 32 + threadIdx.x;
    int yo0 = blockIdx.x * 32;
#pragma unroll
    for (int r = 0; r < 4; r++) {
        int yo = yo0 + threadIdx.y + r * 8;
        g_T[(size_t)yo * 32768 + xo] = to_tf32(tile[threadIdx.x][threadIdx.y + r * 8]);
    }
}

__global__ void prep_w_kernel(const float* __restrict__ W) {
    int idx = blockIdx.x * 256 + threadIdx.x;
    if (idx >= 512 * 896) return;
    int k = idx / 896, c = idx - k * 896;
    float v;
    if (c < 384) v = W[(size_t)k * 896 + c];
    else {
        int cc = c - 384, u = cc >> 2, g = cc & 3;
        v = W[(size_t)k * 896 + 384 + g * 128 + u];
    }
    g_Wp[idx] = to_tf32(v);
}
__global__ void prep_u2_kernel(const float* __restrict__ Umat, const float* __restrict__ w_ij) {
    int idx = blockIdx.x * 256 + threadIdx.x;
    if (idx >= 512 * 128) return;
    int k = idx >> 7;
    g_U2[idx] = to_tf32((k < 384) ? Umat[idx] : w_ij[idx - 384 * 128]);
}
__global__ void prep_b_kernel(const float* __restrict__ bias) {
    int c = blockIdx.x * 256 + threadIdx.x;
    if (c >= 896) return;
    if (c < 384) g_bP[c] = bias[c];
    else {
        int cc = c - 384, u = cc >> 2, g = cc & 3;
        g_bP[c] = bias[384 + g * 128 + u];
    }
}

// ---------------------------------------------------------------------------
#define ASTR 36
#define BSTR 132
#define ASZ  (128 * ASTR)   // floats per A buffer
#define BSZT (32 * BSTR)    // floats per B buffer
#define SMEM_BYTES ((2 * ASZ + 2 * BSZT) * 4)   // 70656

// K1: rz = q @ Wp ; gates in epilogue. grid = (7 n-tiles, nc*2 row-tiles), 256 thr.
__global__ __launch_bounds__(256) void k1_kernel(int d) {
    extern __shared__ float sm[];
    float* Abuf[2] = { sm, sm + ASZ };
    float* Bbuf[2] = { sm + 2 * ASZ, sm + 2 * ASZ + BSZT };

    const int tid = threadIdx.x, lane = tid & 31, warp = tid >> 5;
    const int wm = warp >> 1, wn = warp & 1, qj = lane & 3, ql = lane >> 2;
    const int i0 = (d > 31) ? d - 31 : 0;
    const int Mbase = blockIdx.y * 128;
    const int cell = Mbase >> 8, b0 = Mbase & 255;
    const int i = i0 + cell, j = d - i, p = i * 32 + j;
    const int nc0 = blockIdx.x * 128;

    const float* src[4]; int vld[4];
    vld[0] = (i > 0) ? 16 : 0;
    vld[1] = (j > 0) ? 16 : 0;
    vld[2] = (i > 0 && j > 0) ? 16 : 0;
    vld[3] = 16;
    src[0] = vld[0] ? g_Hr + ((size_t)(p - 32) * BSZ + b0) * 128 : g_T;
    src[1] = vld[1] ? g_Hr + ((size_t)(p - 1 ) * BSZ + b0) * 128 : g_T;
    src[2] = vld[2] ? g_Hr + ((size_t)(p - 33) * BSZ + b0) * 128 : g_T;
    src[3] = g_T + ((size_t)p * BSZ + b0) * 128;

    float acc[2][8][4] = {};

#define STAGE1(t, buf) do {                                                     \
        int seg_ = (t) >> 2;                                                    \
        const float* sp_ = src[seg_]; int v_ = vld[seg_];                       \
        int koff4_ = ((t) & 3) * 8;                                             \
        uint32_t aB_ = (uint32_t)__cvta_generic_to_shared(Abuf[buf]);           \
        uint32_t bB_ = (uint32_t)__cvta_generic_to_shared(Bbuf[buf]);           \
        _Pragma("unroll")                                                       \
        for (int r_ = 0; r_ < 4; r_++) {                                        \
            int idx_ = tid + r_ * 256;                                          \
            int m_ = idx_ >> 3, k4_ = idx_ & 7;                                 \
            cp16(aB_ + (m_ * ASTR + k4_ * 4) * 4,                               \
                 sp_ + (size_t)m_ * 128 + (koff4_ + k4_) * 4, v_);              \
        }                                                                       \
        const float* wp_ = g_Wp + (size_t)(t) * 32 * 896 + nc0;                 \
        _Pragma("unroll")                                                       \
        for (int r_ = 0; r_ < 4; r_++) {                                        \
            int idx_ = tid + r_ * 256;                                          \
            int k_ = idx_ >> 5, n4_ = idx_ & 31;                                \
            cp16(bB_ + (k_ * BSTR + n4_ * 4) * 4,                               \
                 wp_ + (size_t)k_ * 896 + n4_ * 4, 16);                         \
        }                                                                       \
        asm volatile("cp.async.commit_group;");                                 \
    } while (0)

    STAGE1(0, 0);
#pragma unroll 1
    for (int t = 0; t < 16; t++) {
        int buf = t & 1;
        if (t < 15) { STAGE1(t + 1, buf ^ 1); asm volatile("cp.async.wait_group 1;"); }
        else        { asm volatile("cp.async.wait_group 0;"); }
        __syncthreads();
        const uint32_t* A = (const uint32_t*)Abuf[buf];
        const uint32_t* B = (const uint32_t*)Bbuf[buf];
#pragma unroll
        for (int k8 = 0; k8 < 4; k8++) {
            int kb = k8 * 8;
            uint32_t af[2][4];
#pragma unroll
            for (int mt = 0; mt < 2; mt++) {
                int r = wm * 32 + mt * 16 + ql;
                int k = kb + qj;
                af[mt][0] = A[r * ASTR + k];       af[mt][1] = A[(r + 8) * ASTR + k];
                af[mt][2] = A[r * ASTR + k + 4];   af[mt][3] = A[(r + 8) * ASTR + k + 4];
            }
#pragma unroll
            for (int nt = 0; nt < 8; nt++) {
                int n = wn * 64 + nt * 8 + ql;
                int k = kb + qj;
                uint32_t bf[2] = { B[k * BSTR + n], B[(k + 4) * BSTR + n] };
                mma8(acc[0][nt], af[0], bf);
                mma8(acc[1][nt], af[1], bf);
            }
        }
        __syncthreads();
    }

    // ---- epilogue ----
    if (nc0 < 384) {
        // r-region: r = hsig(.); A2 = r * h ; pairing: [0:128)->h_left, ->h_top, ->h_diag
        const float* hsrc[3];
        hsrc[0] = (j > 0)          ? g_H + ((size_t)(p - 1 ) * BSZ + b0) * 128 : nullptr;
        hsrc[1] = (i > 0)          ? g_H + ((size_t)(p - 32) * BSZ + b0) * 128 : nullptr;
        hsrc[2] = (i > 0 && j > 0) ? g_H + ((size_t)(p - 33) * BSZ + b0) * 128 : nullptr;
#pragma unroll
        for (int mt = 0; mt < 2; mt++) {
#pragma unroll
            for (int half = 0; half < 2; half++) {
                int lr = wm * 32 + mt * 16 + ql + half * 8;
                int Mr = Mbase + lr;
#pragma unroll
                for (int nt = 0; nt < 8; nt++) {
                    int c = nc0 + wn * 64 + nt * 8 + 2 * qj;
                    float v0 = acc[mt][nt][half * 2 + 0] + g_bP[c];
                    float v1 = acc[mt][nt][half * 2 + 1] + g_bP[c + 1];
                    v0 = fminf(fmaxf(0.2f * v0 + 0.5f, 0.f), 1.f);
                    v1 = fminf(fmaxf(0.2f * v1 + 0.5f, 0.f), 1.f);
                    int seg = c >> 7, u = c & 127;
                    const float* hp = hsrc[seg];
                    float h0 = hp ? hp[lr * 128 + u]     : 0.f;
                    float h1 = hp ? hp[lr * 128 + u + 1] : 0.f;
                    float2 o = make_float2(to_tf32(v0 * h0), to_tf32(v1 * h1));
                    *(float2*)&g_A2[(size_t)Mr * 384 + c] = o;
                }
            }
        }
    } else {
        // z-region (permuted): groups of 4 adjacent cols; lane-pair softmax
#pragma unroll
        for (int mt = 0; mt < 2; mt++) {
#pragma unroll
            for (int half = 0; half < 2; half++) {
                int lr = wm * 32 + mt * 16 + ql + half * 8;
                int Mr = Mbase + lr;
#pragma unroll
                for (int nt = 0; nt < 8; nt++) {
                    int c = nc0 + wn * 64 + nt * 8 + 2 * qj;
                    float z0 = acc[mt][nt][half * 2 + 0] + g_bP[c];
                    float z1 = acc[mt][nt][half * 2 + 1] + g_bP[c + 1];
                    float q0 = __shfl_xor_sync(0xffffffffu, z0, 1);
                    float q1 = __shfl_xor_sync(0xffffffffu, z1, 1);
                    float mx = fmaxf(fmaxf(z0, z1), fmaxf(q0, q1));
                    float e0 = __expf(z0 - mx), e1 = __expf(z1 - mx);
                    float s2 = e0 + e1;
                    float st = s2 + __shfl_xor_sync(0xffffffffu, s2, 1);
                    float inv = 1.f / st;
                    int cc = c - 384, u = cc >> 2, g = cc & 3;
                    *(float2*)&g_Z[(size_t)Mr * 512 + u * 4 + g] =
                        make_float2(e0 * inv, e1 * inv);
                }
            }
        }
    }
}

// K2: hstar = tanh(A2 @ U2 + b_ij); h = zl*hl + zt*ht + zd*hd + zi*hstar
__global__ __launch_bounds__(256) void k2_kernel(int d, const float* __restrict__ bias,
                                                 float* __restrict__ out) {
    extern __shared__ float sm[];
    float* Abuf[2] = { sm, sm + ASZ };
    float* Bbuf[2] = { sm + 2 * ASZ, sm + 2 * ASZ + BSZT };

    const int tid = threadIdx.x, lane = tid & 31, warp = tid >> 5;
    const int wm = warp >> 1, wn = warp & 1, qj = lane & 3, ql = lane >> 2;
    const int i0 = (d > 31) ? d - 31 : 0;
    const int Mbase = blockIdx.x * 128;
    const int cell = Mbase >> 8, b0 = Mbase & 255;
    const int i = i0 + cell, j = d - i, p = i * 32 + j;

    const float* Tsrc = g_T + ((size_t)p * BSZ + b0) * 128;
    float acc[2][8][4] = {};

#define STAGE2(t, buf) do {                                                     \
        uint32_t aB_ = (uint32_t)__cvta_generic_to_shared(Abuf[buf]);           \
        uint32_t bB_ = (uint32_t)__cvta_generic_to_shared(Bbuf[buf]);           \
        int tk_ = (t) * 32;                                                     \
        _Pragma("unroll")                                                       \
        for (int r_ = 0; r_ < 4; r_++) {                                        \
            int idx_ = tid + r_ * 256;                                          \
            int m_ = idx_ >> 3, k4_ = idx_ & 7;                                 \
            const float* sp_;                                                   \
            if ((t) < 12) sp_ = g_A2 + (size_t)(Mbase + m_) * 384 + tk_ + k4_ * 4; \
            else          sp_ = Tsrc + (size_t)m_ * 128 + (tk_ - 384) + k4_ * 4;   \
            cp16(aB_ + (m_ * ASTR + k4_ * 4) * 4, sp_, 16);                     \
        }                                                                       \
        _Pragma("unroll")                                                       \
        for (int r_ = 0; r_ < 4; r_++) {                                        \
            int idx_ = tid + r_ * 256;                                          \
            int k_ = idx_ >> 5, n4_ = idx_ & 31;                                \
            cp16(bB_ + (k_ * BSTR + n4_ * 4) * 4,                               \
                 g_U2 + (size_t)(tk_ + k_) * 128 + n4_ * 4, 16);                \
        }                                                                       \
        asm volatile("cp.async.commit_group;");                                 \
    } while (0)

    STAGE2(0, 0);
#pragma unroll 1
    for (int t = 0; t < 16; t++) {
        int buf = t & 1;
        if (t < 15) { STAGE2(t + 1, buf ^ 1); asm volatile("cp.async.wait_group 1;"); }
        else        { asm volatile("cp.async.wait_group 0;"); }
        __syncthreads();
        const uint32_t* A = (const uint32_t*)Abuf[buf];
        const uint32_t* B = (const uint32_t*)Bbuf[buf];
#pragma unroll
        for (int k8 = 0; k8 < 4; k8++) {
            int kb = k8 * 8;
            uint32_t af[2][4];
#pragma unroll
            for (int mt = 0; mt < 2; mt++) {
                int r = wm * 32 + mt * 16 + ql;
                int k = kb + qj;
                af[mt][0] = A[r * ASTR + k];       af[mt][1] = A[(r + 8) * ASTR + k];
                af[mt][2] = A[r * ASTR + k + 4];   af[mt][3] = A[(r + 8) * ASTR + k + 4];
            }
#pragma unroll
            for (int nt = 0; nt < 8; nt++) {
                int n = wn * 64 + nt * 8 + ql;
                int k = kb + qj;
                uint32_t bf[2] = { B[k * BSTR + n], B[(k + 4) * BSTR + n] };
                mma8(acc[0][nt], af[0], bf);
                mma8(acc[1][nt], af[1], bf);
            }
        }
        __syncthreads();
    }

    const float* hL = (j > 0)          ? g_H + ((size_t)(p - 1 ) * BSZ + b0) * 128 : nullptr;
    const float* hT = (i > 0)          ? g_H + ((size_t)(p - 32) * BSZ + b0) * 128 : nullptr;
    const float* hD = (i > 0 && j > 0) ? g_H + ((size_t)(p - 33) * BSZ + b0) * 128 : nullptr;
    float* Hd  = g_H  + ((size_t)p * BSZ + b0) * 128;
    float* Hrd = g_Hr + ((size_t)p * BSZ + b0) * 128;

#pragma unroll
    for (int mt = 0; mt < 2; mt++) {
#pragma unroll
        for (int half = 0; half < 2; half++) {
            int lr = wm * 32 + mt * 16 + ql + half * 8;
            int Mr = Mbase + lr;
#pragma unroll
            for (int nt = 0; nt < 8; nt++) {
                int u = wn * 64 + nt * 8 + 2 * qj;
                float a0 = acc[mt][nt][half * 2 + 0] + bias[896 + u];
                float a1 = acc[mt][nt][half * 2 + 1] + bias[896 + u + 1];
                float hs0 = tanhf(a0), hs1 = tanhf(a1);
                float4 z0 = *(const float4*)&g_Z[(size_t)Mr * 512 + u * 4];
                float4 z1 = *(const float4*)&g_Z[(size_t)Mr * 512 + (u + 1) * 4];
                float l0 = hL ? hL[lr * 128 + u] : 0.f, l1 = hL ? hL[lr * 128 + u + 1] : 0.f;
                float t0 = hT ? hT[lr * 128 + u] : 0.f, t1 = hT ? hT[lr * 128 + u + 1] : 0.f;
                float d0 = hD ? hD[lr * 128 + u] : 0.f, d1 = hD ? hD[lr * 128 + u + 1] : 0.f;
                float h0 = z0.y * l0 + z0.z * t0 + z0.w * d0 + z0.x * hs0;
                float h1 = z1.y * l1 + z1.z * t1 + z1.w * d1 + z1.x * hs1;
                *(float2*)&Hd [lr * 128 + u] = make_float2(h0, h1);
                *(float2*)&Hrd[lr * 128 + u] = make_float2(to_tf32(h0), to_tf32(h1));
                if (p == 1023)
                    *(float2*)&out[(size_t)(b0 + lr) * 128 + u] = make_float2(h0, h1);
            }
        }
    }
}

// ---------------------------------------------------------------------------
extern "C" void kernel_launch(void* const* d_in, const int* in_sizes, int n_in,
                              void* d_out, int out_size) {
    const float* inputs = (const float*)d_in[0];
    const float* W      = (const float*)d_in[1];
    const float* Umat   = (const float*)d_in[2];
    const float* bias   = (const float*)d_in[3];
    const float* w_ij   = (const float*)d_in[4];
    float* out = (float*)d_out;

    cudaFuncSetAttribute(k1_kernel, cudaFuncAttributeMaxDynamicSharedMemorySize, SMEM_BYTES);
    cudaFuncSetAttribute(k2_kernel, cudaFuncAttributeMaxDynamicSharedMemorySize, SMEM_BYTES);

    transpose_kernel<<<dim3(32, 1024), dim3(32, 8)>>>(inputs);
    prep_w_kernel<<<(512 * 896 + 255) / 256, 256>>>(W);
    prep_u2_kernel<<<(512 * 128 + 255) / 256, 256>>>(Umat, w_ij);
    prep_b_kernel<<<4, 256>>>(bias);

    for (int d = 0; d <= 62; d++) {
        int i0 = (d > 31) ? d - 31 : 0;
        int i1 = (d < 31) ? d : 31;
        int nc = i1 - i0 + 1;
        k1_kernel<<<dim3(7, nc * 2), 256, SMEM_BYTES>>>(d);
        k2_kernel<<<dim3(nc * 2), 256, SMEM_BYTES>>>(d, bias, out);
    }
    (void)in_sizes; (void)n_in; (void)out_size;
}